// round 2
// baseline (speedup 1.0000x reference)
#include <cuda_runtime.h>
#include <cuda_bf16.h>
#include <cstdint>

// Problem constants
#define NN   100000     // nodes
#define NE   1600000    // edges
#define FIN  128        // input features
#define HID  64         // hidden
#define NC   32         // classes

// ---------------- device scratch (static allocation only) ----------------
__device__ float g_deg [NN];
__device__ float g_dinv[NN];
__device__ float g_hs  [NN * HID];   // (X@W) * dinv[row]   (scaled linear output)
__device__ float g_agg [NN * HID];   // scatter accumulator
__device__ float g_h   [NN * HID];   // relu'd layer output

// ---------------- degree / dinv ----------------
__global__ void k_deg_init() {
    int i = blockIdx.x * blockDim.x + threadIdx.x;
    if (i < NN) g_deg[i] = 1.0f;     // self-loop
}

__global__ void k_deg_count(const int* __restrict__ dst) {
    int e = blockIdx.x * blockDim.x + threadIdx.x;
    if (e < NE) atomicAdd(&g_deg[dst[e]], 1.0f);
}

__global__ void k_dinv() {
    int i = blockIdx.x * blockDim.x + threadIdx.x;
    if (i < NN) g_dinv[i] = rsqrtf(g_deg[i]);
}

// ---------------- GEMM: hs[row][col] = dinv[row] * sum_k X[row][k]*W[k][col]
// Also zeroes g_agg for the subsequent scatter.
// Block: 256 threads -> 32 rows x 64 cols, each thread 8 rows x 1 col.
template<int K, bool FROM_GH>
__global__ void k_gemm_scale(const float* __restrict__ X,
                             const float* __restrict__ W)
{
    __shared__ float Ws[K * HID];
    __shared__ float Xs[32 * K];

    const float* Xp = FROM_GH ? g_h : X;
    int tid  = threadIdx.x;
    int row0 = blockIdx.x * 32;

    for (int i = tid; i < K * HID; i += 256) Ws[i] = W[i];
    for (int i = tid; i < 32 * K; i += 256) {
        int r = i / K, k = i - r * K;
        int row = row0 + r;
        Xs[i] = (row < NN) ? Xp[(size_t)row * K + k] : 0.0f;
    }
    // zero agg for this block's rows (coalesced)
    for (int i = tid; i < 32 * HID; i += 256) {
        int row = row0 + i / HID;
        if (row < NN) g_agg[(size_t)row * HID + (i & (HID - 1))] = 0.0f;
    }
    __syncthreads();

    int col = tid & 63;
    int rg  = tid >> 6;            // 0..3 -> rows rg*8 .. rg*8+7
    float acc[8];
#pragma unroll
    for (int j = 0; j < 8; j++) acc[j] = 0.0f;

#pragma unroll 8
    for (int k = 0; k < K; k++) {
        float wv = Ws[k * HID + col];
#pragma unroll
        for (int j = 0; j < 8; j++)
            acc[j] += Xs[(rg * 8 + j) * K + k] * wv;   // Xs read is warp-broadcast
    }

#pragma unroll
    for (int j = 0; j < 8; j++) {
        int row = row0 + rg * 8 + j;
        if (row < NN)
            g_hs[(size_t)row * HID + col] = acc[j] * g_dinv[row];
    }
}

// ---------------- edge scatter: agg[dst] += hs[src] (64 floats = 16 x float4)
// One thread per (edge, float4-chunk). Vector red.global atomics (sm_90+).
__global__ void k_scatter(const int* __restrict__ src, const int* __restrict__ dst)
{
    unsigned int t = blockIdx.x * blockDim.x + threadIdx.x;
    if (t >= (unsigned int)NE * 16u) return;
    int e = t >> 4;
    int p = t & 15;
    int s = __ldg(&src[e]);
    int d = __ldg(&dst[e]);
    float4 v = *reinterpret_cast<const float4*>(&g_hs[(size_t)s * HID + p * 4]);
    float* ap = &g_agg[(size_t)d * HID + p * 4];
    unsigned long long gp = (unsigned long long)__cvta_generic_to_global(ap);
    asm volatile("red.global.add.v4.f32 [%0], {%1,%2,%3,%4};"
                 :: "l"(gp), "f"(v.x), "f"(v.y), "f"(v.z), "f"(v.w)
                 : "memory");
}

// ---------------- finalize: h = relu(dinv[i]*(agg + hs) + b)
__global__ void k_finalize(const float* __restrict__ b)
{
    int t = blockIdx.x * blockDim.x + threadIdx.x;   // over NN*16 float4 chunks
    if (t >= NN * 16) return;
    int i = t >> 4, p = t & 15;
    float dv = g_dinv[i];
    float4 a  = *reinterpret_cast<const float4*>(&g_agg[(size_t)i * HID + p * 4]);
    float4 hv = *reinterpret_cast<const float4*>(&g_hs [(size_t)i * HID + p * 4]);
    float4 bb = *reinterpret_cast<const float4*>(&b[p * 4]);
    float4 o;
    o.x = fmaxf(fmaf(dv, a.x + hv.x, bb.x), 0.0f);
    o.y = fmaxf(fmaf(dv, a.y + hv.y, bb.y), 0.0f);
    o.z = fmaxf(fmaf(dv, a.z + hv.z, bb.z), 0.0f);
    o.w = fmaxf(fmaf(dv, a.w + hv.w, bb.w), 0.0f);
    *reinterpret_cast<float4*>(&g_h[(size_t)i * HID + p * 4]) = o;
}

// ---------------- output head: softmax(h @ Wout + bout)
// One warp per row: 32 lanes = 32 classes; warp-shuffle softmax.
__global__ void k_out(const float* __restrict__ Wout,
                      const float* __restrict__ bout,
                      float* __restrict__ out)
{
    __shared__ float Ws[HID * NC];   // 8 KB
    __shared__ float Hs[8 * HID];    // 2 KB
    int tid = threadIdx.x;
    int row0 = blockIdx.x * 8;

    for (int i = tid; i < HID * NC; i += 256) Ws[i] = Wout[i];
    for (int i = tid; i < 8 * HID; i += 256) {
        int r = row0 + i / HID;
        Hs[i] = (r < NN) ? g_h[(size_t)r * HID + (i & (HID - 1))] : 0.0f;
    }
    __syncthreads();

    int w = tid >> 5, lane = tid & 31;
    int row = row0 + w;
    if (row >= NN) return;

    float acc = bout[lane];
#pragma unroll
    for (int k = 0; k < HID; k++)
        acc += Hs[w * HID + k] * Ws[k * NC + lane];

    // stable softmax over 32 lanes
    float m = acc;
#pragma unroll
    for (int off = 16; off; off >>= 1)
        m = fmaxf(m, __shfl_xor_sync(0xffffffffu, m, off));
    float ex = __expf(acc - m);
    float s = ex;
#pragma unroll
    for (int off = 16; off; off >>= 1)
        s += __shfl_xor_sync(0xffffffffu, s, off);

    out[(size_t)row * NC + lane] = ex / s;
}

// ---------------- launcher ----------------
extern "C" void kernel_launch(void* const* d_in, const int* in_sizes, int n_in,
                              void* d_out, int out_size)
{
    const float* x    = (const float*)d_in[0];
    const int*   ei   = (const int*)  d_in[1];   // [2, E]
    const float* W1   = (const float*)d_in[2];
    const float* b1   = (const float*)d_in[3];
    const float* W2   = (const float*)d_in[4];
    const float* b2   = (const float*)d_in[5];
    const float* Wout = (const float*)d_in[6];
    const float* bout = (const float*)d_in[7];
    float* out = (float*)d_out;

    const int* src = ei;
    const int* dst = ei + NE;

    const int TB = 256;
    int gN    = (NN + TB - 1) / TB;            // 391
    int gE    = (NE + TB - 1) / TB;            // 6250
    int gScat = (NE * 16 + TB - 1) / TB;       // 100000
    int gFin  = (NN * 16 + TB - 1) / TB;       // 6250
    int gGemm = (NN + 31) / 32;                // 3125
    int gOut  = (NN + 7) / 8;                  // 12500

    // degrees (same for both layers)
    k_deg_init <<<gN, TB>>>();
    k_deg_count<<<gE, TB>>>(dst);
    k_dinv     <<<gN, TB>>>();

    // layer 1
    k_gemm_scale<FIN, false><<<gGemm, TB>>>(x, W1);
    k_scatter  <<<gScat, TB>>>(src, dst);
    k_finalize <<<gFin, TB>>>(b1);

    // layer 2
    k_gemm_scale<HID, true><<<gGemm, TB>>>(nullptr, W2);
    k_scatter  <<<gScat, TB>>>(src, dst);
    k_finalize <<<gFin, TB>>>(b2);

    // output head
    k_out<<<gOut, TB>>>(Wout, bout, out);
}

// round 4
// speedup vs baseline: 1.3429x; 1.3429x over previous
#include <cuda_runtime.h>
#include <cuda_bf16.h>
#include <cstdint>

// Problem constants
#define NN   100000     // nodes
#define NE   1600000    // edges
#define FIN  128        // input features
#define HID  64         // hidden
#define NC   32         // classes

// ---------------- device scratch (static allocation only) ----------------
__device__ float g_deg [NN];
__device__ float g_dinv[NN];
__device__ float g_hs  [NN * HID];   // (X@W) * dinv[row]
__device__ float g_agg [NN * HID];   // scatter accumulator
__device__ float g_h   [NN * HID];   // relu'd layer output

// ---------------- degree / dinv ----------------
__global__ void k_deg_init() {
    int i = blockIdx.x * blockDim.x + threadIdx.x;
    if (i < NN) g_deg[i] = 1.0f;     // self-loop
}

__global__ void k_deg_count(const int* __restrict__ dst) {
    int e = blockIdx.x * blockDim.x + threadIdx.x;
    if (e < NE) atomicAdd(&g_deg[dst[e]], 1.0f);
}

__global__ void k_dinv() {
    int i = blockIdx.x * blockDim.x + threadIdx.x;
    if (i < NN) g_dinv[i] = rsqrtf(g_deg[i]);
}

// ---------------- register-tiled GEMM:
// hs[row][col] = dinv[row] * sum_k X[row][k] * W[k][col];  also zeroes g_agg.
// Block: 256 threads, tile 128 rows x 64 cols, K-tiles of 32.
// Thread (tx=tid&15, ty=tid>>4) computes 8 rows x 4 cols.
template<int K, bool FROM_GH>
__global__ __launch_bounds__(256) void k_gemm_scale(const float* __restrict__ X,
                                                    const float* __restrict__ W)
{
    __shared__ float Xs[128 * 32];   // [row][kk] 16KB
    __shared__ float Ws[32 * 64];    // [kk][col]  8KB

    const float* Xp = FROM_GH ? g_h : X;
    const int tid  = threadIdx.x;
    const int row0 = blockIdx.x * 128;
    const int tx = tid & 15;         // col group: cols tx*4 .. tx*4+3
    const int ty = tid >> 4;         // row group: rows ty*8 .. ty*8+7

    // zero agg for this block's rows (coalesced float4 stores)
    {
        const float4 z = make_float4(0.f, 0.f, 0.f, 0.f);
        for (int i = tid; i < 128 * 16; i += 256) {
            int row = row0 + (i >> 4);
            if (row < NN)
                *reinterpret_cast<float4*>(&g_agg[(size_t)row * HID + (i & 15) * 4]) = z;
        }
    }

    float acc[8][4];
#pragma unroll
    for (int j = 0; j < 8; j++)
#pragma unroll
        for (int c = 0; c < 4; c++) acc[j][c] = 0.0f;

    for (int kt = 0; kt < K; kt += 32) {
        // load X tile: 128 rows x 32 k = 1024 float4 (4 per thread)
#pragma unroll
        for (int i = tid; i < 1024; i += 256) {
            int r = i >> 3, f = i & 7;
            int row = row0 + r;
            float4 v = make_float4(0.f, 0.f, 0.f, 0.f);
            if (row < NN)
                v = *reinterpret_cast<const float4*>(&Xp[(size_t)row * K + kt + f * 4]);
            *reinterpret_cast<float4*>(&Xs[r * 32 + f * 4]) = v;
        }
        // load W tile: 32 k x 64 cols = 512 float4 (2 per thread)
#pragma unroll
        for (int i = tid; i < 512; i += 256) {
            int kk = i >> 4, f = i & 15;
            *reinterpret_cast<float4*>(&Ws[kk * 64 + f * 4]) =
                *reinterpret_cast<const float4*>(&W[(size_t)(kt + kk) * 64 + f * 4]);
        }
        __syncthreads();

#pragma unroll
        for (int kk = 0; kk < 32; kk++) {
            float4 wv = *reinterpret_cast<const float4*>(&Ws[kk * 64 + tx * 4]);
#pragma unroll
            for (int j = 0; j < 8; j++) {
                float xv = Xs[(ty * 8 + j) * 32 + kk];   // warp-broadcast
                acc[j][0] = fmaf(xv, wv.x, acc[j][0]);
                acc[j][1] = fmaf(xv, wv.y, acc[j][1]);
                acc[j][2] = fmaf(xv, wv.z, acc[j][2]);
                acc[j][3] = fmaf(xv, wv.w, acc[j][3]);
            }
        }
        __syncthreads();
    }

#pragma unroll
    for (int j = 0; j < 8; j++) {
        int row = row0 + ty * 8 + j;
        if (row < NN) {
            float dv = g_dinv[row];
            float4 o = make_float4(acc[j][0] * dv, acc[j][1] * dv,
                                   acc[j][2] * dv, acc[j][3] * dv);
            *reinterpret_cast<float4*>(&g_hs[(size_t)row * HID + tx * 4]) = o;
        }
    }
}

// ---------------- edge scatter: agg[dst] += hs[src] (64 floats = 16 x float4)
// One thread per (edge, float4-chunk). Vector red.global atomics (sm_90+).
__global__ void k_scatter(const int* __restrict__ src, const int* __restrict__ dst)
{
    unsigned int t = blockIdx.x * blockDim.x + threadIdx.x;
    if (t >= (unsigned int)NE * 16u) return;
    int e = t >> 4;
    int p = t & 15;
    int s = __ldg(&src[e]);
    int d = __ldg(&dst[e]);
    float4 v = *reinterpret_cast<const float4*>(&g_hs[(size_t)s * HID + p * 4]);
    float* ap = &g_agg[(size_t)d * HID + p * 4];
    unsigned long long gp = (unsigned long long)__cvta_generic_to_global(ap);
    asm volatile("red.global.add.v4.f32 [%0], {%1,%2,%3,%4};"
                 :: "l"(gp), "f"(v.x), "f"(v.y), "f"(v.z), "f"(v.w)
                 : "memory");
}

// ---------------- finalize: h = relu(dinv[i]*(agg + hs) + b)
__global__ void k_finalize(const float* __restrict__ b)
{
    int t = blockIdx.x * blockDim.x + threadIdx.x;   // over NN*16 float4 chunks
    if (t >= NN * 16) return;
    int i = t >> 4, p = t & 15;
    float dv = g_dinv[i];
    float4 a  = *reinterpret_cast<const float4*>(&g_agg[(size_t)i * HID + p * 4]);
    float4 hv = *reinterpret_cast<const float4*>(&g_hs [(size_t)i * HID + p * 4]);
    float4 bb = *reinterpret_cast<const float4*>(&b[p * 4]);
    float4 o;
    o.x = fmaxf(fmaf(dv, a.x + hv.x, bb.x), 0.0f);
    o.y = fmaxf(fmaf(dv, a.y + hv.y, bb.y), 0.0f);
    o.z = fmaxf(fmaf(dv, a.z + hv.z, bb.z), 0.0f);
    o.w = fmaxf(fmaf(dv, a.w + hv.w, bb.w), 0.0f);
    *reinterpret_cast<float4*>(&g_h[(size_t)i * HID + p * 4]) = o;
}

// ---------------- output head: softmax(h @ Wout + bout)
// 32 rows per block; warp computes one row at a time (32 lanes = 32 classes).
__global__ __launch_bounds__(256) void k_out(const float* __restrict__ Wout,
                                             const float* __restrict__ bout,
                                             float* __restrict__ out)
{
    __shared__ float Ws[HID * NC];   // 8 KB
    __shared__ float Hs[32 * HID];   // 8 KB
    int tid = threadIdx.x;
    int row0 = blockIdx.x * 32;

    for (int i = tid; i < HID * NC; i += 256) Ws[i] = Wout[i];
    for (int i = tid; i < 32 * HID; i += 256) {
        int r = row0 + (i >> 6);
        Hs[i] = (r < NN) ? g_h[(size_t)r * HID + (i & (HID - 1))] : 0.0f;
    }
    __syncthreads();

    int w = tid >> 5, lane = tid & 31;
    float bo = __ldg(&bout[lane]);

#pragma unroll
    for (int rr = 0; rr < 4; rr++) {
        int lr  = w * 4 + rr;        // local row 0..31
        int row = row0 + lr;
        if (row >= NN) continue;

        float acc = bo;
#pragma unroll
        for (int k = 0; k < HID; k++)
            acc = fmaf(Hs[lr * HID + k], Ws[k * NC + lane], acc);

        // stable softmax over 32 lanes
        float m = acc;
#pragma unroll
        for (int off = 16; off; off >>= 1)
            m = fmaxf(m, __shfl_xor_sync(0xffffffffu, m, off));
        float ex = __expf(acc - m);
        float s = ex;
#pragma unroll
        for (int off = 16; off; off >>= 1)
            s += __shfl_xor_sync(0xffffffffu, s, off);

        out[(size_t)row * NC + lane] = ex / s;
    }
}

// ---------------- launcher ----------------
extern "C" void kernel_launch(void* const* d_in, const int* in_sizes, int n_in,
                              void* d_out, int out_size)
{
    const float* x    = (const float*)d_in[0];
    const int*   ei   = (const int*)  d_in[1];   // [2, E]
    const float* W1   = (const float*)d_in[2];
    const float* b1   = (const float*)d_in[3];
    const float* W2   = (const float*)d_in[4];
    const float* b2   = (const float*)d_in[5];
    const float* Wout = (const float*)d_in[6];
    const float* bout = (const float*)d_in[7];
    float* out = (float*)d_out;

    const int* src = ei;
    const int* dst = ei + NE;

    const int TB = 256;
    int gN    = (NN + TB - 1) / TB;            // 391
    int gE    = (NE + TB - 1) / TB;            // 6250
    int gScat = (NE * 16 + TB - 1) / TB;       // 100000
    int gFin  = (NN * 16 + TB - 1) / TB;       // 6250
    int gGemm = (NN + 127) / 128;              // 782
    int gOut  = (NN + 31) / 32;                // 3125

    // degrees (same for both layers)
    k_deg_init <<<gN, TB>>>();
    k_deg_count<<<gE, TB>>>(dst);
    k_dinv     <<<gN, TB>>>();

    // layer 1
    k_gemm_scale<FIN, false><<<gGemm, TB>>>(x, W1);
    k_scatter  <<<gScat, TB>>>(src, dst);
    k_finalize <<<gFin, TB>>>(b1);

    // layer 2
    k_gemm_scale<HID, true><<<gGemm, TB>>>(nullptr, W2);
    k_scatter  <<<gScat, TB>>>(src, dst);
    k_finalize <<<gFin, TB>>>(b2);

    // output head
    k_out<<<gOut, TB>>>(Wout, bout, out);
}

// round 6
// speedup vs baseline: 1.7911x; 1.3338x over previous
#include <cuda_runtime.h>
#include <cuda_bf16.h>
#include <cstdint>

// Problem constants
#define NN   100000     // nodes
#define NE   1600000    // edges
#define FIN  128        // input features
#define HID  64         // hidden
#define NC   32         // classes

#define SCAN_BLK 512
#define NBS ((NN + SCAN_BLK - 1) / SCAN_BLK)   // 196

// ---------------- device scratch (static allocation only) ----------------
__device__ int   g_cnt [NN];        // in-degree (excl. self-loop)
__device__ int   g_off [NN];        // CSR offsets (exclusive prefix of cnt)
__device__ int   g_cur [NN];        // fill cursors
__device__ int   g_csr [NE];        // src ids grouped by dst
__device__ int   g_bsum[NBS];       // scan block sums
__device__ float g_dinv[NN];
__device__ float g_hs  [NN * HID];  // (X@W) * dinv[row]
__device__ float g_h   [NN * HID];  // relu'd layer output

// ---------------- degree counting / dinv ----------------
__global__ void k_zero_cnt() {
    int i = blockIdx.x * blockDim.x + threadIdx.x;
    if (i < NN) g_cnt[i] = 0;
}

__global__ void k_count(const int* __restrict__ dst) {
    int e = blockIdx.x * blockDim.x + threadIdx.x;
    if (e < NE) atomicAdd(&g_cnt[dst[e]], 1);
}

__global__ void k_dinv() {
    int i = blockIdx.x * blockDim.x + threadIdx.x;
    if (i < NN) g_dinv[i] = rsqrtf((float)g_cnt[i] + 1.0f);   // + self-loop
}

// ---------------- CSR build: 3-step scan + bucket fill ----------------
__global__ void k_scan_blocksum() {
    __shared__ int sm[SCAN_BLK];
    int t = threadIdx.x;
    int i = blockIdx.x * SCAN_BLK + t;
    sm[t] = (i < NN) ? g_cnt[i] : 0;
    __syncthreads();
#pragma unroll
    for (int s = SCAN_BLK / 2; s > 0; s >>= 1) {
        if (t < s) sm[t] += sm[t + s];
        __syncthreads();
    }
    if (t == 0) g_bsum[blockIdx.x] = sm[0];
}

__global__ void k_scan_bsum() {     // single block of 256, NBS=196 <= 256
    __shared__ int sm[256];
    int t = threadIdx.x;
    int orig = (t < NBS) ? g_bsum[t] : 0;
    sm[t] = orig;
    __syncthreads();
#pragma unroll
    for (int d = 1; d < 256; d <<= 1) {
        int v = (t >= d) ? sm[t - d] : 0;
        __syncthreads();
        sm[t] += v;
        __syncthreads();
    }
    if (t < NBS) g_bsum[t] = sm[t] - orig;   // exclusive
}

__global__ void k_scan_write() {
    __shared__ int sm[SCAN_BLK];
    int t = threadIdx.x;
    int i = blockIdx.x * SCAN_BLK + t;
    int v = (i < NN) ? g_cnt[i] : 0;
    sm[t] = v;
    __syncthreads();
#pragma unroll
    for (int d = 1; d < SCAN_BLK; d <<= 1) {
        int u = (t >= d) ? sm[t - d] : 0;
        __syncthreads();
        sm[t] += u;
        __syncthreads();
    }
    if (i < NN) {
        int off = g_bsum[blockIdx.x] + sm[t] - v;   // exclusive prefix
        g_off[i] = off;
        g_cur[i] = off;
    }
}

__global__ void k_fill(const int* __restrict__ src, const int* __restrict__ dst) {
    int e = blockIdx.x * blockDim.x + threadIdx.x;
    if (e < NE) {
        int d = dst[e];
        int pos = atomicAdd(&g_cur[d], 1);
        g_csr[pos] = src[e];
    }
}

// ---------------- register-tiled GEMM:
// hs[row][col] = dinv[row] * sum_k X[row][k] * W[k][col]
// Block: 256 threads, tile 128 rows x 64 cols, K-tiles of 32.
template<int K, bool FROM_GH>
__global__ __launch_bounds__(256) void k_gemm_scale(const float* __restrict__ X,
                                                    const float* __restrict__ W)
{
    __shared__ float Xs[128 * 32];   // [row][kk] 16KB
    __shared__ float Ws[32 * 64];    // [kk][col]  8KB

    const float* Xp = FROM_GH ? g_h : X;
    const int tid  = threadIdx.x;
    const int row0 = blockIdx.x * 128;
    const int tx = tid & 15;         // cols tx*4 .. tx*4+3
    const int ty = tid >> 4;         // rows ty*8 .. ty*8+7

    float acc[8][4];
#pragma unroll
    for (int j = 0; j < 8; j++)
#pragma unroll
        for (int c = 0; c < 4; c++) acc[j][c] = 0.0f;

    for (int kt = 0; kt < K; kt += 32) {
#pragma unroll
        for (int i = tid; i < 1024; i += 256) {
            int r = i >> 3, f = i & 7;
            int row = row0 + r;
            float4 v = make_float4(0.f, 0.f, 0.f, 0.f);
            if (row < NN)
                v = *reinterpret_cast<const float4*>(&Xp[(size_t)row * K + kt + f * 4]);
            *reinterpret_cast<float4*>(&Xs[r * 32 + f * 4]) = v;
        }
#pragma unroll
        for (int i = tid; i < 512; i += 256) {
            int kk = i >> 4, f = i & 15;
            *reinterpret_cast<float4*>(&Ws[kk * 64 + f * 4]) =
                *reinterpret_cast<const float4*>(&W[(size_t)(kt + kk) * 64 + f * 4]);
        }
        __syncthreads();

#pragma unroll
        for (int kk = 0; kk < 32; kk++) {
            float4 wv = *reinterpret_cast<const float4*>(&Ws[kk * 64 + tx * 4]);
#pragma unroll
            for (int j = 0; j < 8; j++) {
                float xv = Xs[(ty * 8 + j) * 32 + kk];   // warp-broadcast
                acc[j][0] = fmaf(xv, wv.x, acc[j][0]);
                acc[j][1] = fmaf(xv, wv.y, acc[j][1]);
                acc[j][2] = fmaf(xv, wv.z, acc[j][2]);
                acc[j][3] = fmaf(xv, wv.w, acc[j][3]);
            }
        }
        __syncthreads();
    }

#pragma unroll
    for (int j = 0; j < 8; j++) {
        int row = row0 + ty * 8 + j;
        if (row < NN) {
            float dv = g_dinv[row];
            float4 o = make_float4(acc[j][0] * dv, acc[j][1] * dv,
                                   acc[j][2] * dv, acc[j][3] * dv);
            *reinterpret_cast<float4*>(&g_hs[(size_t)row * HID + tx * 4]) = o;
        }
    }
}

// ---------------- gather-aggregate-finalize:
// h[i] = relu(dinv[i] * (sum_{e: dst=i} hs[src_e] + hs[i]) + b)
// One warp per node; lane covers features (lane, lane+32).
__global__ __launch_bounds__(256) void k_gather_fin(const float* __restrict__ b)
{
    int w = (blockIdx.x * 256 + threadIdx.x) >> 5;
    if (w >= NN) return;
    int lane = threadIdx.x & 31;

    int off = __ldg(&g_off[w]);
    int cnt = __ldg(&g_cnt[w]);

    float a0 = 0.f, a1 = 0.f, c0 = 0.f, c1 = 0.f;
    int j = 0;
    for (; j + 4 <= cnt; j += 4) {
        int s0 = __ldg(&g_csr[off + j]);
        int s1 = __ldg(&g_csr[off + j + 1]);
        int s2 = __ldg(&g_csr[off + j + 2]);
        int s3 = __ldg(&g_csr[off + j + 3]);
        const float* p0 = &g_hs[(size_t)s0 * HID + lane];
        const float* p1 = &g_hs[(size_t)s1 * HID + lane];
        const float* p2 = &g_hs[(size_t)s2 * HID + lane];
        const float* p3 = &g_hs[(size_t)s3 * HID + lane];
        a0 += __ldg(p0);      a1 += __ldg(p0 + 32);
        c0 += __ldg(p1);      c1 += __ldg(p1 + 32);
        a0 += __ldg(p2);      a1 += __ldg(p2 + 32);
        c0 += __ldg(p3);      c1 += __ldg(p3 + 32);
    }
    for (; j < cnt; j++) {
        int s = __ldg(&g_csr[off + j]);
        const float* p = &g_hs[(size_t)s * HID + lane];
        a0 += __ldg(p);
        a1 += __ldg(p + 32);
    }
    a0 += c0;
    a1 += c1;

    // self-loop term + finalize
    const float* ps = &g_hs[(size_t)w * HID + lane];
    float hv0 = __ldg(ps), hv1 = __ldg(ps + 32);
    float dv  = g_dinv[w];
    float bb0 = __ldg(&b[lane]), bb1 = __ldg(&b[32 + lane]);

    g_h[(size_t)w * HID + lane]      = fmaxf(fmaf(dv, a0 + hv0, bb0), 0.f);
    g_h[(size_t)w * HID + 32 + lane] = fmaxf(fmaf(dv, a1 + hv1, bb1), 0.f);
}

// ---------------- output head: softmax(h @ Wout + bout) ----------------
__global__ __launch_bounds__(256) void k_out(const float* __restrict__ Wout,
                                             const float* __restrict__ bout,
                                             float* __restrict__ out)
{
    __shared__ float Ws[HID * NC];   // 8 KB
    __shared__ float Hs[32 * HID];   // 8 KB
    int tid = threadIdx.x;
    int row0 = blockIdx.x * 32;

    for (int i = tid; i < HID * NC; i += 256) Ws[i] = Wout[i];
    for (int i = tid; i < 32 * HID; i += 256) {
        int r = row0 + (i >> 6);
        Hs[i] = (r < NN) ? g_h[(size_t)r * HID + (i & (HID - 1))] : 0.0f;
    }
    __syncthreads();

    int w = tid >> 5, lane = tid & 31;
    float bo = __ldg(&bout[lane]);

#pragma unroll
    for (int rr = 0; rr < 4; rr++) {
        int lr  = w * 4 + rr;
        int row = row0 + lr;
        if (row >= NN) continue;

        float acc = bo;
#pragma unroll
        for (int k = 0; k < HID; k++)
            acc = fmaf(Hs[lr * HID + k], Ws[k * NC + lane], acc);

        float m = acc;
#pragma unroll
        for (int off = 16; off; off >>= 1)
            m = fmaxf(m, __shfl_xor_sync(0xffffffffu, m, off));
        float ex = __expf(acc - m);
        float s = ex;
#pragma unroll
        for (int off = 16; off; off >>= 1)
            s += __shfl_xor_sync(0xffffffffu, s, off);

        out[(size_t)row * NC + lane] = ex / s;
    }
}

// ---------------- launcher ----------------
extern "C" void kernel_launch(void* const* d_in, const int* in_sizes, int n_in,
                              void* d_out, int out_size)
{
    const float* x    = (const float*)d_in[0];
    const int*   ei   = (const int*)  d_in[1];   // [2, E]
    const float* W1   = (const float*)d_in[2];
    const float* b1   = (const float*)d_in[3];
    const float* W2   = (const float*)d_in[4];
    const float* b2   = (const float*)d_in[5];
    const float* Wout = (const float*)d_in[6];
    const float* bout = (const float*)d_in[7];
    float* out = (float*)d_out;

    const int* src = ei;
    const int* dst = ei + NE;

    const int TB = 256;
    int gN    = (NN + TB - 1) / TB;            // 391
    int gE    = (NE + TB - 1) / TB;            // 6250
    int gGemm = (NN + 127) / 128;              // 782
    int gGath = (NN * 32 + TB - 1) / TB;       // 12500 (one warp per node)
    int gOut  = (NN + 31) / 32;                // 3125

    // CSR build (shared by both layers)
    k_zero_cnt     <<<gN, TB>>>();
    k_count        <<<gE, TB>>>(dst);
    k_dinv         <<<gN, TB>>>();
    k_scan_blocksum<<<NBS, SCAN_BLK>>>();
    k_scan_bsum    <<<1, 256>>>();
    k_scan_write   <<<NBS, SCAN_BLK>>>();
    k_fill         <<<gE, TB>>>(src, dst);

    // layer 1
    k_gemm_scale<FIN, false><<<gGemm, TB>>>(x, W1);
    k_gather_fin<<<gGath, TB>>>(b1);

    // layer 2
    k_gemm_scale<HID, true><<<gGemm, TB>>>(nullptr, W2);
    k_gather_fin<<<gGath, TB>>>(b2);

    // output head
    k_out<<<gOut, TB>>>(Wout, bout, out);
}

// round 7
// speedup vs baseline: 1.9570x; 1.0926x over previous
#include <cuda_runtime.h>
#include <cuda_bf16.h>
#include <cstdint>

// Problem constants
#define NN   100000     // nodes
#define NE   1600000    // edges
#define FIN  128        // input features
#define HID  64         // hidden
#define NC   32         // classes

#define SCAN_BLK 512
#define NBS ((NN + SCAN_BLK - 1) / SCAN_BLK)   // 196

// ---------------- device scratch (static allocation only) ----------------
__device__ int   g_cnt [NN];        // in-degree (excl. self-loop)
__device__ int   g_off [NN];        // CSR offsets (exclusive prefix of cnt)
__device__ int   g_cur [NN];        // fill cursors
__device__ int   g_csr [NE];        // src ids grouped by dst
__device__ int   g_bsum[NBS];       // scan block sums
__device__ float g_dinv[NN];
__device__ float g_hs  [NN * HID];  // (X@W) * dinv[row]
__device__ float g_h   [NN * HID];  // relu'd layer output

// ---------------- degree counting ----------------
__global__ void k_zero_cnt() {
    int i = blockIdx.x * blockDim.x + threadIdx.x;
    if (i < NN) g_cnt[i] = 0;
}

__global__ void k_count(const int* __restrict__ dst) {
    int e = blockIdx.x * blockDim.x + threadIdx.x;
    if (e < NE) atomicAdd(&g_cnt[dst[e]], 1);
}

// ---------------- CSR build: 3-step scan + bucket fill ----------------
__global__ void k_scan_blocksum() {
    __shared__ int sm[SCAN_BLK];
    int t = threadIdx.x;
    int i = blockIdx.x * SCAN_BLK + t;
    sm[t] = (i < NN) ? g_cnt[i] : 0;
    __syncthreads();
#pragma unroll
    for (int s = SCAN_BLK / 2; s > 0; s >>= 1) {
        if (t < s) sm[t] += sm[t + s];
        __syncthreads();
    }
    if (t == 0) g_bsum[blockIdx.x] = sm[0];
}

__global__ void k_scan_bsum() {     // single block of 256, NBS=196 <= 256
    __shared__ int sm[256];
    int t = threadIdx.x;
    int orig = (t < NBS) ? g_bsum[t] : 0;
    sm[t] = orig;
    __syncthreads();
#pragma unroll
    for (int d = 1; d < 256; d <<= 1) {
        int v = (t >= d) ? sm[t - d] : 0;
        __syncthreads();
        sm[t] += v;
        __syncthreads();
    }
    if (t < NBS) g_bsum[t] = sm[t] - orig;   // exclusive
}

__global__ void k_scan_write() {    // also computes dinv (fused)
    __shared__ int sm[SCAN_BLK];
    int t = threadIdx.x;
    int i = blockIdx.x * SCAN_BLK + t;
    int v = (i < NN) ? g_cnt[i] : 0;
    sm[t] = v;
    __syncthreads();
#pragma unroll
    for (int d = 1; d < SCAN_BLK; d <<= 1) {
        int u = (t >= d) ? sm[t - d] : 0;
        __syncthreads();
        sm[t] += u;
        __syncthreads();
    }
    if (i < NN) {
        int off = g_bsum[blockIdx.x] + sm[t] - v;   // exclusive prefix
        g_off[i] = off;
        g_cur[i] = off;
        g_dinv[i] = rsqrtf((float)v + 1.0f);        // + self-loop
    }
}

__global__ void k_fill(const int* __restrict__ src, const int* __restrict__ dst) {
    int e = blockIdx.x * blockDim.x + threadIdx.x;
    if (e < NE) {
        int d = dst[e];
        int pos = atomicAdd(&g_cur[d], 1);
        g_csr[pos] = src[e];
    }
}

// ---------------- register-tiled GEMM:
// hs[row][col] = dinv[row] * sum_k X[row][k] * W[k][col]
// Block: 256 threads, tile 128 rows x 64 cols, K-tiles of 32.
template<int K, bool FROM_GH>
__global__ __launch_bounds__(256) void k_gemm_scale(const float* __restrict__ X,
                                                    const float* __restrict__ W)
{
    __shared__ float Xs[128 * 32];   // [row][kk] 16KB
    __shared__ float Ws[32 * 64];    // [kk][col]  8KB

    const float* Xp = FROM_GH ? g_h : X;
    const int tid  = threadIdx.x;
    const int row0 = blockIdx.x * 128;
    const int tx = tid & 15;         // cols tx*4 .. tx*4+3
    const int ty = tid >> 4;         // rows ty*8 .. ty*8+7

    float acc[8][4];
#pragma unroll
    for (int j = 0; j < 8; j++)
#pragma unroll
        for (int c = 0; c < 4; c++) acc[j][c] = 0.0f;

    for (int kt = 0; kt < K; kt += 32) {
#pragma unroll
        for (int i = tid; i < 1024; i += 256) {
            int r = i >> 3, f = i & 7;
            int row = row0 + r;
            float4 v = make_float4(0.f, 0.f, 0.f, 0.f);
            if (row < NN)
                v = *reinterpret_cast<const float4*>(&Xp[(size_t)row * K + kt + f * 4]);
            *reinterpret_cast<float4*>(&Xs[r * 32 + f * 4]) = v;
        }
#pragma unroll
        for (int i = tid; i < 512; i += 256) {
            int kk = i >> 4, f = i & 15;
            *reinterpret_cast<float4*>(&Ws[kk * 64 + f * 4]) =
                *reinterpret_cast<const float4*>(&W[(size_t)(kt + kk) * 64 + f * 4]);
        }
        __syncthreads();

#pragma unroll
        for (int kk = 0; kk < 32; kk++) {
            float4 wv = *reinterpret_cast<const float4*>(&Ws[kk * 64 + tx * 4]);
#pragma unroll
            for (int j = 0; j < 8; j++) {
                float xv = Xs[(ty * 8 + j) * 32 + kk];   // warp-broadcast
                acc[j][0] = fmaf(xv, wv.x, acc[j][0]);
                acc[j][1] = fmaf(xv, wv.y, acc[j][1]);
                acc[j][2] = fmaf(xv, wv.z, acc[j][2]);
                acc[j][3] = fmaf(xv, wv.w, acc[j][3]);
            }
        }
        __syncthreads();
    }

#pragma unroll
    for (int j = 0; j < 8; j++) {
        int row = row0 + ty * 8 + j;
        if (row < NN) {
            float dv = g_dinv[row];
            float4 o = make_float4(acc[j][0] * dv, acc[j][1] * dv,
                                   acc[j][2] * dv, acc[j][3] * dv);
            *reinterpret_cast<float4*>(&g_hs[(size_t)row * HID + tx * 4]) = o;
        }
    }
}

// ---------------- gather-aggregate-finalize (vectorized):
// h[i] = relu(dinv[i] * (sum_{e: dst=i} hs[src_e] + hs[i]) + b)
// One warp per node. Lane layout: half = lane>>4 selects edge slot,
// c4 = lane&15 selects a float4 feature chunk (16 x float4 = 64 floats).
// Two edges in flight per iteration step, 2 accumulators for MLP.
__global__ __launch_bounds__(256) void k_gather_fin(const float* __restrict__ b)
{
    int w = (blockIdx.x * 256 + threadIdx.x) >> 5;
    if (w >= NN) return;
    const int lane = threadIdx.x & 31;
    const int half = lane >> 4;          // 0 or 1: which edge of the pair
    const int c4   = lane & 15;          // float4 chunk index

    const int off = __ldg(&g_off[w]);
    const int cnt = __ldg(&g_cnt[w]);

    float4 acc  = make_float4(0.f, 0.f, 0.f, 0.f);
    float4 acc2 = make_float4(0.f, 0.f, 0.f, 0.f);

    int j = 0;
    for (; j + 4 <= cnt; j += 4) {
        int s0 = __ldg(&g_csr[off + j + half]);        // broadcast within half
        int s1 = __ldg(&g_csr[off + j + 2 + half]);
        float4 v0 = *reinterpret_cast<const float4*>(&g_hs[(size_t)s0 * HID + c4 * 4]);
        float4 v1 = *reinterpret_cast<const float4*>(&g_hs[(size_t)s1 * HID + c4 * 4]);
        acc.x  += v0.x; acc.y  += v0.y; acc.z  += v0.z; acc.w  += v0.w;
        acc2.x += v1.x; acc2.y += v1.y; acc2.z += v1.z; acc2.w += v1.w;
    }
    for (; j < cnt; j += 2) {                          // tail: up to 3 edges
        if (j + half < cnt) {
            int s = __ldg(&g_csr[off + j + half]);
            float4 v = *reinterpret_cast<const float4*>(&g_hs[(size_t)s * HID + c4 * 4]);
            acc.x += v.x; acc.y += v.y; acc.z += v.z; acc.w += v.w;
        }
    }
    acc.x += acc2.x; acc.y += acc2.y; acc.z += acc2.z; acc.w += acc2.w;

    // cross-half reduction: lane l += lane l^16
    acc.x += __shfl_xor_sync(0xffffffffu, acc.x, 16);
    acc.y += __shfl_xor_sync(0xffffffffu, acc.y, 16);
    acc.z += __shfl_xor_sync(0xffffffffu, acc.z, 16);
    acc.w += __shfl_xor_sync(0xffffffffu, acc.w, 16);

    if (half == 0) {
        float4 hv = *reinterpret_cast<const float4*>(&g_hs[(size_t)w * HID + c4 * 4]);
        float dv  = g_dinv[w];
        float4 bb = *reinterpret_cast<const float4*>(&b[c4 * 4]);
        float4 o;
        o.x = fmaxf(fmaf(dv, acc.x + hv.x, bb.x), 0.f);
        o.y = fmaxf(fmaf(dv, acc.y + hv.y, bb.y), 0.f);
        o.z = fmaxf(fmaf(dv, acc.z + hv.z, bb.z), 0.f);
        o.w = fmaxf(fmaf(dv, acc.w + hv.w, bb.w), 0.f);
        *reinterpret_cast<float4*>(&g_h[(size_t)w * HID + c4 * 4]) = o;
    }
}

// ---------------- output head: softmax(h @ Wout + bout) ----------------
__global__ __launch_bounds__(256) void k_out(const float* __restrict__ Wout,
                                             const float* __restrict__ bout,
                                             float* __restrict__ out)
{
    __shared__ float Ws[HID * NC];   // 8 KB
    __shared__ float Hs[32 * HID];   // 8 KB
    int tid = threadIdx.x;
    int row0 = blockIdx.x * 32;

    for (int i = tid; i < HID * NC; i += 256) Ws[i] = Wout[i];
    for (int i = tid; i < 32 * HID; i += 256) {
        int r = row0 + (i >> 6);
        Hs[i] = (r < NN) ? g_h[(size_t)r * HID + (i & (HID - 1))] : 0.0f;
    }
    __syncthreads();

    int w = tid >> 5, lane = tid & 31;
    float bo = __ldg(&bout[lane]);

#pragma unroll
    for (int rr = 0; rr < 4; rr++) {
        int lr  = w * 4 + rr;
        int row = row0 + lr;
        if (row >= NN) continue;

        float acc = bo;
#pragma unroll
        for (int k = 0; k < HID; k++)
            acc = fmaf(Hs[lr * HID + k], Ws[k * NC + lane], acc);

        float m = acc;
#pragma unroll
        for (int off = 16; off; off >>= 1)
            m = fmaxf(m, __shfl_xor_sync(0xffffffffu, m, off));
        float ex = __expf(acc - m);
        float s = ex;
#pragma unroll
        for (int off = 16; off; off >>= 1)
            s += __shfl_xor_sync(0xffffffffu, s, off);

        out[(size_t)row * NC + lane] = ex / s;
    }
}

// ---------------- launcher ----------------
extern "C" void kernel_launch(void* const* d_in, const int* in_sizes, int n_in,
                              void* d_out, int out_size)
{
    const float* x    = (const float*)d_in[0];
    const int*   ei   = (const int*)  d_in[1];   // [2, E]
    const float* W1   = (const float*)d_in[2];
    const float* b1   = (const float*)d_in[3];
    const float* W2   = (const float*)d_in[4];
    const float* b2   = (const float*)d_in[5];
    const float* Wout = (const float*)d_in[6];
    const float* bout = (const float*)d_in[7];
    float* out = (float*)d_out;

    const int* src = ei;
    const int* dst = ei + NE;

    const int TB = 256;
    int gN    = (NN + TB - 1) / TB;            // 391
    int gE    = (NE + TB - 1) / TB;            // 6250
    int gGemm = (NN + 127) / 128;              // 782
    int gGath = (NN * 32 + TB - 1) / TB;       // 12500 (one warp per node)
    int gOut  = (NN + 31) / 32;                // 3125

    // CSR build (shared by both layers); dinv fused into scan_write
    k_zero_cnt     <<<gN, TB>>>();
    k_count        <<<gE, TB>>>(dst);
    k_scan_blocksum<<<NBS, SCAN_BLK>>>();
    k_scan_bsum    <<<1, 256>>>();
    k_scan_write   <<<NBS, SCAN_BLK>>>();
    k_fill         <<<gE, TB>>>(src, dst);

    // layer 1
    k_gemm_scale<FIN, false><<<gGemm, TB>>>(x, W1);
    k_gather_fin<<<gGath, TB>>>(b1);

    // layer 2
    k_gemm_scale<HID, true><<<gGemm, TB>>>(nullptr, W2);
    k_gather_fin<<<gGath, TB>>>(b2);

    // output head
    k_out<<<gOut, TB>>>(Wout, bout, out);
}

// round 8
// speedup vs baseline: 2.0687x; 1.0571x over previous
#include <cuda_runtime.h>
#include <cuda_bf16.h>
#include <cstdint>

// Problem constants
#define NN   100000     // nodes
#define NE   1600000    // edges
#define FIN  128        // input features
#define HID  64         // hidden
#define NC   32         // classes

#define SCAN_BLK 512
#define NBS ((NN + SCAN_BLK - 1) / SCAN_BLK)   // 196

// ---------------- device scratch (static allocation only) ----------------
__device__ int   g_cnt [NN];        // in-degree (excl. self-loop)
__device__ int   g_off [NN];        // CSR offsets (exclusive prefix of cnt)
__device__ int   g_cur [NN];        // fill cursors
__device__ int   g_csr [NE];        // src ids grouped by dst
__device__ int   g_bsum[NBS];       // scan block sums
__device__ float g_dinv[NN];
__device__ float g_hs  [NN * HID];  // (X@W) * dinv[row]
__device__ float g_h   [NN * HID];  // relu'd layer output

// ---------------- degree counting / dinv ----------------
__global__ void k_zero_cnt() {
    int i = blockIdx.x * blockDim.x + threadIdx.x;
    if (i < NN) g_cnt[i] = 0;
}

__global__ void k_count(const int* __restrict__ dst) {
    int e = blockIdx.x * blockDim.x + threadIdx.x;
    if (e < NE) atomicAdd(&g_cnt[dst[e]], 1);
}

__global__ void k_dinv() {
    int i = blockIdx.x * blockDim.x + threadIdx.x;
    if (i < NN) g_dinv[i] = rsqrtf((float)g_cnt[i] + 1.0f);   // + self-loop
}

// ---------------- CSR build: 3-step scan + bucket fill ----------------
__global__ void k_scan_blocksum() {
    __shared__ int sm[SCAN_BLK];
    int t = threadIdx.x;
    int i = blockIdx.x * SCAN_BLK + t;
    sm[t] = (i < NN) ? g_cnt[i] : 0;
    __syncthreads();
#pragma unroll
    for (int s = SCAN_BLK / 2; s > 0; s >>= 1) {
        if (t < s) sm[t] += sm[t + s];
        __syncthreads();
    }
    if (t == 0) g_bsum[blockIdx.x] = sm[0];
}

__global__ void k_scan_bsum() {     // single block of 256, NBS=196 <= 256
    __shared__ int sm[256];
    int t = threadIdx.x;
    int orig = (t < NBS) ? g_bsum[t] : 0;
    sm[t] = orig;
    __syncthreads();
#pragma unroll
    for (int d = 1; d < 256; d <<= 1) {
        int v = (t >= d) ? sm[t - d] : 0;
        __syncthreads();
        sm[t] += v;
        __syncthreads();
    }
    if (t < NBS) g_bsum[t] = sm[t] - orig;   // exclusive
}

__global__ void k_scan_write() {
    __shared__ int sm[SCAN_BLK];
    int t = threadIdx.x;
    int i = blockIdx.x * SCAN_BLK + t;
    int v = (i < NN) ? g_cnt[i] : 0;
    sm[t] = v;
    __syncthreads();
#pragma unroll
    for (int d = 1; d < SCAN_BLK; d <<= 1) {
        int u = (t >= d) ? sm[t - d] : 0;
        __syncthreads();
        sm[t] += u;
        __syncthreads();
    }
    if (i < NN) {
        int off = g_bsum[blockIdx.x] + sm[t] - v;   // exclusive prefix
        g_off[i] = off;
        g_cur[i] = off;
    }
}

__global__ void k_fill(const int* __restrict__ src, const int* __restrict__ dst) {
    int e = blockIdx.x * blockDim.x + threadIdx.x;
    if (e < NE) {
        int d = dst[e];
        int pos = atomicAdd(&g_cur[d], 1);
        g_csr[pos] = src[e];
    }
}

// ---------------- register-tiled GEMM:
// hs[row][col] = dinv[row] * sum_k X[row][k] * W[k][col]
// Block: 256 threads, tile 128 rows x 64 cols, K-tiles of 32.
template<int K, bool FROM_GH>
__global__ __launch_bounds__(256) void k_gemm_scale(const float* __restrict__ X,
                                                    const float* __restrict__ W)
{
    __shared__ float Xs[128 * 32];   // [row][kk] 16KB
    __shared__ float Ws[32 * 64];    // [kk][col]  8KB

    const float* Xp = FROM_GH ? g_h : X;
    const int tid  = threadIdx.x;
    const int row0 = blockIdx.x * 128;
    const int tx = tid & 15;         // cols tx*4 .. tx*4+3
    const int ty = tid >> 4;         // rows ty*8 .. ty*8+7

    float acc[8][4];
#pragma unroll
    for (int j = 0; j < 8; j++)
#pragma unroll
        for (int c = 0; c < 4; c++) acc[j][c] = 0.0f;

    for (int kt = 0; kt < K; kt += 32) {
#pragma unroll
        for (int i = tid; i < 1024; i += 256) {
            int r = i >> 3, f = i & 7;
            int row = row0 + r;
            float4 v = make_float4(0.f, 0.f, 0.f, 0.f);
            if (row < NN)
                v = *reinterpret_cast<const float4*>(&Xp[(size_t)row * K + kt + f * 4]);
            *reinterpret_cast<float4*>(&Xs[r * 32 + f * 4]) = v;
        }
#pragma unroll
        for (int i = tid; i < 512; i += 256) {
            int kk = i >> 4, f = i & 15;
            *reinterpret_cast<float4*>(&Ws[kk * 64 + f * 4]) =
                *reinterpret_cast<const float4*>(&W[(size_t)(kt + kk) * 64 + f * 4]);
        }
        __syncthreads();

#pragma unroll
        for (int kk = 0; kk < 32; kk++) {
            float4 wv = *reinterpret_cast<const float4*>(&Ws[kk * 64 + tx * 4]);
#pragma unroll
            for (int j = 0; j < 8; j++) {
                float xv = Xs[(ty * 8 + j) * 32 + kk];   // warp-broadcast
                acc[j][0] = fmaf(xv, wv.x, acc[j][0]);
                acc[j][1] = fmaf(xv, wv.y, acc[j][1]);
                acc[j][2] = fmaf(xv, wv.z, acc[j][2]);
                acc[j][3] = fmaf(xv, wv.w, acc[j][3]);
            }
        }
        __syncthreads();
    }

#pragma unroll
    for (int j = 0; j < 8; j++) {
        int row = row0 + ty * 8 + j;
        if (row < NN) {
            float dv = g_dinv[row];
            float4 o = make_float4(acc[j][0] * dv, acc[j][1] * dv,
                                   acc[j][2] * dv, acc[j][3] * dv);
            *reinterpret_cast<float4*>(&g_hs[(size_t)row * HID + tx * 4]) = o;
        }
    }
}

// ---------------- gather-aggregate-finalize (vectorized):
// h[i] = relu(dinv[i] * (sum_{e: dst=i} hs[src_e] + hs[i]) + b)
// One warp per node. Lane layout: half = lane>>4 selects edge slot,
// c4 = lane&15 selects a float4 feature chunk (16 x float4 = 64 floats).
__global__ __launch_bounds__(256) void k_gather_fin(const float* __restrict__ b)
{
    int w = (blockIdx.x * 256 + threadIdx.x) >> 5;
    if (w >= NN) return;
    const int lane = threadIdx.x & 31;
    const int half = lane >> 4;          // 0 or 1: which edge of the pair
    const int c4   = lane & 15;          // float4 chunk index

    const int off = __ldg(&g_off[w]);
    const int cnt = __ldg(&g_cnt[w]);

    float4 acc  = make_float4(0.f, 0.f, 0.f, 0.f);
    float4 acc2 = make_float4(0.f, 0.f, 0.f, 0.f);

    int j = 0;
    for (; j + 4 <= cnt; j += 4) {
        int s0 = __ldg(&g_csr[off + j + half]);        // broadcast within half
        int s1 = __ldg(&g_csr[off + j + 2 + half]);
        float4 v0 = *reinterpret_cast<const float4*>(&g_hs[(size_t)s0 * HID + c4 * 4]);
        float4 v1 = *reinterpret_cast<const float4*>(&g_hs[(size_t)s1 * HID + c4 * 4]);
        acc.x  += v0.x; acc.y  += v0.y; acc.z  += v0.z; acc.w  += v0.w;
        acc2.x += v1.x; acc2.y += v1.y; acc2.z += v1.z; acc2.w += v1.w;
    }
    for (; j < cnt; j += 2) {                          // tail: up to 3 edges
        if (j + half < cnt) {
            int s = __ldg(&g_csr[off + j + half]);
            float4 v = *reinterpret_cast<const float4*>(&g_hs[(size_t)s * HID + c4 * 4]);
            acc.x += v.x; acc.y += v.y; acc.z += v.z; acc.w += v.w;
        }
    }
    acc.x += acc2.x; acc.y += acc2.y; acc.z += acc2.z; acc.w += acc2.w;

    // cross-half reduction: lane l += lane l^16
    acc.x += __shfl_xor_sync(0xffffffffu, acc.x, 16);
    acc.y += __shfl_xor_sync(0xffffffffu, acc.y, 16);
    acc.z += __shfl_xor_sync(0xffffffffu, acc.z, 16);
    acc.w += __shfl_xor_sync(0xffffffffu, acc.w, 16);

    if (half == 0) {
        float4 hv = *reinterpret_cast<const float4*>(&g_hs[(size_t)w * HID + c4 * 4]);
        float dv  = g_dinv[w];
        float4 bb = *reinterpret_cast<const float4*>(&b[c4 * 4]);
        float4 o;
        o.x = fmaxf(fmaf(dv, acc.x + hv.x, bb.x), 0.f);
        o.y = fmaxf(fmaf(dv, acc.y + hv.y, bb.y), 0.f);
        o.z = fmaxf(fmaf(dv, acc.z + hv.z, bb.z), 0.f);
        o.w = fmaxf(fmaf(dv, acc.w + hv.w, bb.w), 0.f);
        *reinterpret_cast<float4*>(&g_h[(size_t)w * HID + c4 * 4]) = o;
    }
}

// ---------------- output head: softmax(h @ Wout + bout) ----------------
__global__ __launch_bounds__(256) void k_out(const float* __restrict__ Wout,
                                             const float* __restrict__ bout,
                                             float* __restrict__ out)
{
    __shared__ float Ws[HID * NC];   // 8 KB
    __shared__ float Hs[32 * HID];   // 8 KB
    int tid = threadIdx.x;
    int row0 = blockIdx.x * 32;

    for (int i = tid; i < HID * NC; i += 256) Ws[i] = Wout[i];
    for (int i = tid; i < 32 * HID; i += 256) {
        int r = row0 + (i >> 6);
        Hs[i] = (r < NN) ? g_h[(size_t)r * HID + (i & (HID - 1))] : 0.0f;
    }
    __syncthreads();

    int w = tid >> 5, lane = tid & 31;
    float bo = __ldg(&bout[lane]);

#pragma unroll
    for (int rr = 0; rr < 4; rr++) {
        int lr  = w * 4 + rr;
        int row = row0 + lr;
        if (row >= NN) continue;

        float acc = bo;
#pragma unroll
        for (int k = 0; k < HID; k++)
            acc = fmaf(Hs[lr * HID + k], Ws[k * NC + lane], acc);

        float m = acc;
#pragma unroll
        for (int off = 16; off; off >>= 1)
            m = fmaxf(m, __shfl_xor_sync(0xffffffffu, m, off));
        float ex = __expf(acc - m);
        float s = ex;
#pragma unroll
        for (int off = 16; off; off >>= 1)
            s += __shfl_xor_sync(0xffffffffu, s, off);

        out[(size_t)row * NC + lane] = ex / s;
    }
}

// ---------------- stream/event handles (created once; no device mem) -----
struct ForkHandles {
    cudaStream_t s2;
    cudaEvent_t  eFork, eJoin;
    ForkHandles() {
        cudaStreamCreateWithFlags(&s2, cudaStreamNonBlocking);
        cudaEventCreateWithFlags(&eFork, cudaEventDisableTiming);
        cudaEventCreateWithFlags(&eJoin, cudaEventDisableTiming);
    }
};

// ---------------- launcher ----------------
extern "C" void kernel_launch(void* const* d_in, const int* in_sizes, int n_in,
                              void* d_out, int out_size)
{
    static ForkHandles fh;   // same capture structure on every call

    const float* x    = (const float*)d_in[0];
    const int*   ei   = (const int*)  d_in[1];   // [2, E]
    const float* W1   = (const float*)d_in[2];
    const float* b1   = (const float*)d_in[3];
    const float* W2   = (const float*)d_in[4];
    const float* b2   = (const float*)d_in[5];
    const float* Wout = (const float*)d_in[6];
    const float* bout = (const float*)d_in[7];
    float* out = (float*)d_out;

    const int* src = ei;
    const int* dst = ei + NE;

    const int TB = 256;
    int gN    = (NN + TB - 1) / TB;            // 391
    int gE    = (NE + TB - 1) / TB;            // 6250
    int gGemm = (NN + 127) / 128;              // 782
    int gGath = (NN * 32 + TB - 1) / TB;       // 12500 (one warp per node)
    int gOut  = (NN + 31) / 32;                // 3125

    // ---- counts (needed by both GEMM1-via-dinv and the CSR chain) ----
    k_zero_cnt<<<gN, TB>>>();
    k_count   <<<gE, TB>>>(dst);

    // ---- fork: CSR scan/fill chain runs parallel to dinv+GEMM1 ----
    cudaEventRecord(fh.eFork, 0);
    cudaStreamWaitEvent(fh.s2, fh.eFork, 0);

    k_scan_blocksum<<<NBS, SCAN_BLK, 0, fh.s2>>>();
    k_scan_bsum    <<<1, 256,        0, fh.s2>>>();
    k_scan_write   <<<NBS, SCAN_BLK, 0, fh.s2>>>();
    k_fill         <<<gE, TB,        0, fh.s2>>>(src, dst);
    cudaEventRecord(fh.eJoin, fh.s2);

    // main branch: dinv + layer-1 GEMM (independent of scan/fill)
    k_dinv<<<gN, TB>>>();
    k_gemm_scale<FIN, false><<<gGemm, TB>>>(x, W1);

    // ---- join: gather needs both GEMM1 (g_hs) and CSR (g_off/g_csr) ----
    cudaStreamWaitEvent(0, fh.eJoin, 0);

    // layer 1 aggregation
    k_gather_fin<<<gGath, TB>>>(b1);

    // layer 2
    k_gemm_scale<HID, true><<<gGemm, TB>>>(nullptr, W2);
    k_gather_fin<<<gGath, TB>>>(b2);

    // output head
    k_out<<<gOut, TB>>>(Wout, bout, out);
}